// round 11
// baseline (speedup 1.0000x reference)
#include <cuda_runtime.h>
#include <cuda_bf16.h>
#include <cuda_fp16.h>
#include <math.h>
#include <stdint.h>

// Problem constants
#define BATCH 16
#define NPATCH 4096
#define KTOK 32
#define DIM 512
#define DHEAD 256
#define SCALE_V 0.0625f   // 256^-0.5

#define SPLITS 8          // fused grid = 8 x 16 = 128 blocks (512 thr, occ 1)

// Scratch (no allocation allowed -> device globals)
__device__ __half g_Qkh [BATCH*KTOK*DIM];
__device__ float  g_Gp  [SPLITS*BATCH*KTOK*DIM];
__device__ float  g_G   [BATCH*KTOK*DIM];
__device__ float  g_F   [BATCH*KTOK*DHEAD];
__device__ float  g_rows[BATCH*KTOK*SPLITS];

// ---------------------------------------------------------------------------

#define LDSM4(R0,R1,R2,R3,ADDR) \
    asm volatile("ldmatrix.sync.aligned.m8n8.x4.shared.b16 {%0,%1,%2,%3}, [%4];" \
        : "=r"(R0),"=r"(R1),"=r"(R2),"=r"(R3) : "r"(ADDR))

#define LDSM4T(R0,R1,R2,R3,ADDR) \
    asm volatile("ldmatrix.sync.aligned.m8n8.x4.trans.shared.b16 {%0,%1,%2,%3}, [%4];" \
        : "=r"(R0),"=r"(R1),"=r"(R2),"=r"(R3) : "r"(ADDR))

#define MMA_F16(C,A,B0,B1) \
    asm volatile("mma.sync.aligned.m16n8k16.row.col.f32.f16.f16.f32 " \
        "{%0,%1,%2,%3},{%4,%5,%6,%7},{%8,%9},{%0,%1,%2,%3};" \
        : "+f"((C)[0]),"+f"((C)[1]),"+f"((C)[2]),"+f"((C)[3]) \
        : "r"((A)[0]),"r"((A)[1]),"r"((A)[2]),"r"((A)[3]),"r"(B0),"r"(B1))

__device__ __forceinline__ uint32_t cvta_s(const void* p) {
    return (uint32_t)__cvta_generic_to_shared(p);
}

__device__ __forceinline__ uint2 cvt_h4(float4 v) {
    __half2 h0 = __floats2half2_rn(v.x, v.y);
    __half2 h1 = __floats2half2_rn(v.z, v.w);
    uint2 r; r.x = *(uint32_t*)&h0; r.y = *(uint32_t*)&h1; return r;
}

// fp16 hi/lo split (effective precision ~2^-22)
__device__ __forceinline__ void cvt_split4h(float4 v, uint2 &hi, uint2 &lo) {
    __half2 h0 = __floats2half2_rn(v.x, v.y);
    __half2 h1 = __floats2half2_rn(v.z, v.w);
    float rx = v.x - __half2float(h0.x);
    float ry = v.y - __half2float(h0.y);
    float rz = v.z - __half2float(h1.x);
    float rw = v.w - __half2float(h1.y);
    __half2 l0 = __floats2half2_rn(rx, ry);
    __half2 l1 = __floats2half2_rn(rz, rw);
    hi.x = *(uint32_t*)&h0; hi.y = *(uint32_t*)&h1;
    lo.x = *(uint32_t*)&l0; lo.y = *(uint32_t*)&l1;
}

// ===========================================================================
// FUSED attention kernel v5 — producer/consumer warp specialization.
// Block = (split sp, batch b), 512 thr (8 consumer warps + 8 producer warps),
// occ 1. 8 chunks of 64 E-rows, double-buffered:
//   producers: stage chunk c+1 (fp32->fp16) into buf[(c+1)&1]
//   consumers: phase1 S=Qk@E^T on buf[c&1] -> exp/A-out/ES -> (bar1)
//              phase2 accG += expS@E
//   __syncthreads at chunk end = buffer handoff.
// ===========================================================================
#define QK_OFF   0
#define QK_PITCH 1040
#define E0_OFF   33280
#define E_BUF    66560         // 64 rows x 1040
#define E_PITCH  1040
#define ES_OFF   166400        // E0_OFF + 2*E_BUF
#define ES_PITCH 144
#define RED_OFF  171008        // ES_OFF + 32*144
#define LP_OFF   171520        // RED_OFF + 512
#define SMEM_FUSED 173568      // LP_OFF + 2048

__global__ __launch_bounds__(512, 1)
void fused_attn5(const __half* __restrict__ Qkh, const float* __restrict__ E,
                 const float* __restrict__ P, float* __restrict__ outA,
                 float* __restrict__ Gp, float* __restrict__ rows)
{
    extern __shared__ __align__(16) unsigned char sm[];
    const int sp = blockIdx.x;         // 0..7
    const int b  = blockIdx.y;         // 0..15
    const int tid  = threadIdx.x;
    const int lane = tid & 31;
    const int warp = tid >> 5;
    const bool consumer = (tid < 256);
    const int mw = (warp & 7) >> 2;    // consumer layout
    const int nw = warp & 3;

    const float*  Eb  = E   + (long)b*NPATCH*DIM;
    const __half* Qkb = Qkh + (long)b*KTOK*DIM;
    const float*  Pb  = P   + (long)b*NPATCH;
    float*        Ab  = outA + (long)b*KTOK*NPATCH;

    const int nbase = sp * (NPATCH/SPLITS);   // 512-row slice

    // ---- initial staging ----
    if (consumer) {
        // Qk [32,512] fp16 raw copy (64 x 16B segs per row)
        #pragma unroll
        for (int p = 0; p < 8; ++p) {
            int lin = tid + p*256;
            int r = lin >> 6, seg = lin & 63;
            uint4 v = *(const uint4*)(Qkb + r*DIM + seg*8);
            *(uint4*)(sm + QK_OFF + r*QK_PITCH + seg*16) = v;
        }
        // logP for the 512-col slice (2 entries per consumer thread)
        float* LPw = (float*)(sm + LP_OFF);
        #pragma unroll
        for (int p = 0; p < 2; ++p) {
            int i = tid + p*256;
            float pv = Pb[nbase + i];
            LPw[i] = __logf(fminf(fmaxf(pv, 0.1f), 0.9f));
        }
    } else {
        // producers: stage chunk 0 into buffer 0
        int ptid = tid - 256;
        const float* src = Eb + (long)nbase*DIM;
        #pragma unroll 8
        for (int p = 0; p < 32; ++p) {
            int lin = ptid + p*256;
            int r = lin >> 7, c4 = lin & 127;
            float4 v = *(const float4*)(src + (long)r*DIM + 4*c4);
            *(uint2*)(sm + E0_OFF + r*E_PITCH + 8*c4) = cvt_h4(v);
        }
    }
    __syncthreads();

    float accG[16][4];
    #pragma unroll
    for (int t2 = 0; t2 < 16; ++t2)
        #pragma unroll
        for (int r = 0; r < 4; ++r) accG[t2][r] = 0.f;
    float rsum0 = 0.f, rsum8 = 0.f;

    const uint32_t smb = cvta_s(sm);
    const uint32_t aQkBase = smb + QK_OFF + (mw*16 + (lane & 15))*QK_PITCH + (lane >> 4)*16;
    const uint32_t b1Base0 = smb + E0_OFF
        + (nw*16 + (lane & 7) + ((lane >> 4) & 1)*8)*E_PITCH + ((lane >> 3) & 1)*16;
    const uint32_t aEsBase = smb + ES_OFF + (mw*16 + (lane & 15))*ES_PITCH + (lane >> 4)*16;
    const uint32_t b2Base0 = smb + E0_OFF + (lane & 15)*E_PITCH + nw*256 + ((lane >> 4) & 1)*16;
    const float* LPs = (const float*)(sm + LP_OFF);

    for (int c = 0; c < 8; ++c) {
        const uint32_t bsel = (c & 1)*E_BUF;

        if (!consumer) {
            // ---- producers: stage chunk c+1 into the other buffer ----
            if (c < 7) {
                int ptid = tid - 256;
                const uint32_t bufn = E0_OFF + ((c+1) & 1)*E_BUF;
                const float* src = Eb + (long)(nbase + (c+1)*64)*DIM;
                #pragma unroll 8
                for (int p = 0; p < 32; ++p) {
                    int lin = ptid + p*256;
                    int r = lin >> 7, c4 = lin & 127;
                    float4 v = *(const float4*)(src + (long)r*DIM + 4*c4);
                    *(uint2*)(sm + bufn + r*E_PITCH + 8*c4) = cvt_h4(v);
                }
            }
        } else {
            // ---- consumers: phase 1: S = Qk @ Echunk^T ----
            const int n0 = nbase + c*64;
            float sacc[2][4];
            #pragma unroll
            for (int j = 0; j < 2; ++j)
                #pragma unroll
                for (int r = 0; r < 4; ++r) sacc[j][r] = 0.f;
            const uint32_t b1 = b1Base0 + bsel;
            #pragma unroll
            for (int ks = 0; ks < 32; ++ks) {
                uint32_t a[4], r0, r1, r2, r3;
                LDSM4(a[0],a[1],a[2],a[3], aQkBase + ks*32);
                LDSM4(r0,r1,r2,r3, b1 + ks*32);
                MMA_F16(sacc[0], a, r0, r1);
                MMA_F16(sacc[1], a, r2, r3);
            }

            // epilogue: exp + A(unnorm) + ES smem + rowsums
            {
                const int mrow = mw*16 + (lane >> 2);
                #pragma unroll
                for (int j = 0; j < 2; ++j) {
                    int nl = nw*16 + j*8 + 2*(lane & 3);
                    int gn = n0 + nl;
                    float lp0 = LPs[c*64 + nl];
                    float lp1 = LPs[c*64 + nl + 1];
                    float v0 = __expf(sacc[j][0]*SCALE_V + lp0);
                    float v1 = __expf(sacc[j][1]*SCALE_V + lp1);
                    float v2 = __expf(sacc[j][2]*SCALE_V + lp0);
                    float v3 = __expf(sacc[j][3]*SCALE_V + lp1);
                    rsum0 += v0 + v1; rsum8 += v2 + v3;
                    *(float2*)(Ab + (long)mrow*NPATCH + gn)     = make_float2(v0, v1);
                    *(float2*)(Ab + (long)(mrow+8)*NPATCH + gn) = make_float2(v2, v3);
                    __half2 h01 = __floats2half2_rn(v0, v1);
                    __half2 h23 = __floats2half2_rn(v2, v3);
                    *(uint32_t*)(sm + ES_OFF + mrow*ES_PITCH + nl*2)     = *(uint32_t*)&h01;
                    *(uint32_t*)(sm + ES_OFF + (mrow+8)*ES_PITCH + nl*2) = *(uint32_t*)&h23;
                }
            }
            // consumer-only barrier: ES visible before phase 2
            asm volatile("bar.sync 1, 256;" ::: "memory");

            // ---- phase 2: accG += expS[32,64] @ Echunk[64,512] ----
            const uint32_t b2 = b2Base0 + bsel;
            #pragma unroll
            for (int ks = 0; ks < 4; ++ks) {
                uint32_t a[4];
                LDSM4(a[0],a[1],a[2],a[3], aEsBase + ks*32);
                #pragma unroll
                for (int jt = 0; jt < 8; ++jt) {
                    uint32_t r0, r1, r2, r3;
                    LDSM4T(r0,r1,r2,r3, b2 + ks*16*E_PITCH + jt*32);
                    MMA_F16(accG[2*jt],   a, r0, r1);
                    MMA_F16(accG[2*jt+1], a, r2, r3);
                }
            }
        }
        __syncthreads();   // buffer handoff
    }

    // ---- consumers: write G partial + rowsum partials ----
    if (consumer) {
        float* Gpb = Gp + ((long)(b*SPLITS + sp)*KTOK)*DIM;
        const int mrow = mw*16 + (lane >> 2);
        #pragma unroll
        for (int t2 = 0; t2 < 16; ++t2) {
            int d = nw*128 + t2*8 + 2*(lane & 3);
            *(float2*)(Gpb + (long)mrow*DIM + d)     = make_float2(accG[t2][0], accG[t2][1]);
            *(float2*)(Gpb + (long)(mrow+8)*DIM + d) = make_float2(accG[t2][2], accG[t2][3]);
        }

        rsum0 += __shfl_xor_sync(0xffffffffu, rsum0, 1);
        rsum0 += __shfl_xor_sync(0xffffffffu, rsum0, 2);
        rsum8 += __shfl_xor_sync(0xffffffffu, rsum8, 1);
        rsum8 += __shfl_xor_sync(0xffffffffu, rsum8, 2);
        float (*srow)[4] = (float(*)[4])(sm + RED_OFF);
        if ((lane & 3) == 0) {
            srow[mw*16 + (lane >> 2)][nw]     = rsum0;
            srow[mw*16 + 8 + (lane >> 2)][nw] = rsum8;
        }
    }
    __syncthreads();
    if (tid < 32) {
        float (*srow)[4] = (float(*)[4])(sm + RED_OFF);
        float s = srow[tid][0] + srow[tid][1] + srow[tid][2] + srow[tid][3];
        rows[(b*KTOK + tid)*SPLITS + sp] = s;
    }
}

// ===========================================================================
// post kernel: blocks [0,256) reduce G partials; blocks [256,768) scale A rows.
// ===========================================================================
__global__ __launch_bounds__(256)
void post_kernel(const float* __restrict__ Gp, float* __restrict__ G,
                 const float* __restrict__ rows, float* __restrict__ A)
{
    if (blockIdx.x < 256) {
        int i = blockIdx.x*256 + threadIdx.x;
        int bb  = i >> 12;
        int rem = i & 4095;
        const float4* p = (const float4*)Gp + ((long)bb*SPLITS)*4096 + rem;
        float4 s = make_float4(0.f, 0.f, 0.f, 0.f);
        #pragma unroll
        for (int s2 = 0; s2 < SPLITS; ++s2) {
            float4 v = p[(long)s2*4096];
            s.x += v.x; s.y += v.y; s.z += v.z; s.w += v.w;
        }
        ((float4*)G)[i] = s;
    } else {
        int r = blockIdx.x - 256;
        float s = 0.f;
        #pragma unroll
        for (int c = 0; c < SPLITS; ++c) s += rows[r*SPLITS + c];
        float inv = 1.f / s;
        float4* pa = (float4*)(A + (long)r*NPATCH);
        #pragma unroll
        for (int q = 0; q < 4; ++q) {
            int idx = threadIdx.x + q*256;
            float4 v = pa[idx];
            v.x *= inv; v.y *= inv; v.z *= inv; v.w *= inv;
            pa[idx] = v;
        }
    }
}

// ===========================================================================
// proj_qk (unchanged — verified).
// ===========================================================================
#define PJ_T     0
#define PJ_W     2560
#define PJ_Q     23040
#define PJ_BYTES 39936
#define QS_PITCH 528

__global__ __launch_bounds__(256)
void proj_qk(const float* __restrict__ T, const float* __restrict__ Wq,
             const float* __restrict__ Wk, __half* __restrict__ Qkh)
{
    __shared__ __align__(16) unsigned char sm[PJ_BYTES];
    const int nb = blockIdx.x;
    const int b  = blockIdx.y;
    const int tid  = threadIdx.x;
    const int lane = tid & 31;
    const int warp = tid >> 5;
    const int mw = warp >> 2;
    const int nw = warp & 3;

    const float* Tb = T + (long)b*KTOK*DIM;

    float accQ[8][4];
    #pragma unroll
    for (int j = 0; j < 8; ++j)
        #pragma unroll
        for (int r = 0; r < 4; ++r) accQ[j][r] = 0.f;

    const uint32_t aT = cvta_s(sm + PJ_T)
        + (mw*16 + (lane & 15))*80 + (lane >> 4)*16;
    uint32_t bW[4];
    #pragma unroll
    for (int jj = 0; jj < 4; ++jj)
        bW[jj] = cvta_s(sm + PJ_W)
            + (nw*64 + jj*16 + (lane & 7) + ((lane >> 4) & 1)*8)*80
            + ((lane >> 3) & 1)*16;

    const int am = tid >> 3, ak4 = tid & 7;

    float4 pt, pw[8];
    pt = *(const float4*)(Tb + am*DIM + 4*ak4);
    #pragma unroll
    for (int p = 0; p < 8; ++p) {
        int lin = tid + p*256;
        pw[p] = *(const float4*)(Wq + (long)(lin >> 3)*DIM + 4*(lin & 7));
    }

    for (int k0 = 0; k0 < DIM; k0 += 32) {
        *(uint2*)(sm + PJ_T + am*80 + 8*ak4) = cvt_h4(pt);
        #pragma unroll
        for (int p = 0; p < 8; ++p) {
            int lin = tid + p*256;
            *(uint2*)(sm + PJ_W + (lin >> 3)*80 + 8*(lin & 7)) = cvt_h4(pw[p]);
        }
        __syncthreads();

        int kn = k0 + 32;
        if (kn < DIM) {
            pt = *(const float4*)(Tb + am*DIM + kn + 4*ak4);
            #pragma unroll
            for (int p = 0; p < 8; ++p) {
                int lin = tid + p*256;
                pw[p] = *(const float4*)(Wq + (long)(lin >> 3)*DIM + kn + 4*(lin & 7));
            }
        }

        #pragma unroll
        for (int kt = 0; kt < 2; ++kt) {
            uint32_t a[4];
            LDSM4(a[0],a[1],a[2],a[3], aT + kt*32);
            #pragma unroll
            for (int jj = 0; jj < 4; ++jj) {
                uint32_t r0,r1,r2,r3;
                LDSM4(r0,r1,r2,r3, bW[jj] + kt*32);
                MMA_F16(accQ[2*jj],   a, r0, r1);
                MMA_F16(accQ[2*jj+1], a, r2, r3);
            }
        }
        __syncthreads();
    }

    const int mrow = mw*16 + (lane >> 2);
    #pragma unroll
    for (int j = 0; j < 8; ++j) {
        int col = nw*64 + j*8 + 2*(lane & 3);
        __half2 h01 = __floats2half2_rn(accQ[j][0], accQ[j][1]);
        __half2 h23 = __floats2half2_rn(accQ[j][2], accQ[j][3]);
        *(uint32_t*)(sm + PJ_Q + mrow*QS_PITCH + col*2)     = *(uint32_t*)&h01;
        *(uint32_t*)(sm + PJ_Q + (mrow+8)*QS_PITCH + col*2) = *(uint32_t*)&h23;
    }
    __syncthreads();

    float accK[4][4];
    #pragma unroll
    for (int j = 0; j < 4; ++j)
        #pragma unroll
        for (int r = 0; r < 4; ++r) accK[j][r] = 0.f;

    const uint32_t aQ = cvta_s(sm + PJ_Q)
        + (mw*16 + (lane & 15))*QS_PITCH + (lane >> 4)*16;
    uint32_t bK[2];
    #pragma unroll
    for (int jj = 0; jj < 2; ++jj)
        bK[jj] = cvta_s(sm + PJ_W) + (lane & 15)*272
            + (nw*32 + jj*16)*2 + ((lane >> 4) & 1)*16;

    const int n0 = nb*128;
    float4 pk[4];
    #pragma unroll
    for (int p = 0; p < 4; ++p) {
        int lin = tid + p*256;
        pk[p] = *(const float4*)(Wk + (long)(lin >> 5)*DIM + n0 + 4*(lin & 31));
    }

    for (int k0 = 0; k0 < DHEAD; k0 += 32) {
        #pragma unroll
        for (int p = 0; p < 4; ++p) {
            int lin = tid + p*256;
            *(uint2*)(sm + PJ_W + (lin >> 5)*272 + 8*(lin & 31)) = cvt_h4(pk[p]);
        }
        __syncthreads();

        int kn = k0 + 32;
        if (kn < DHEAD) {
            #pragma unroll
            for (int p = 0; p < 4; ++p) {
                int lin = tid + p*256;
                pk[p] = *(const float4*)(Wk + (long)(kn + (lin >> 5))*DIM + n0 + 4*(lin & 31));
            }
        }

        #pragma unroll
        for (int kt = 0; kt < 2; ++kt) {
            uint32_t a[4];
            LDSM4(a[0],a[1],a[2],a[3], aQ + k0*2 + kt*32);
            #pragma unroll
            for (int jj = 0; jj < 2; ++jj) {
                uint32_t r0,r1,r2,r3;
                LDSM4T(r0,r1,r2,r3, bK[jj] + kt*16*272);
                MMA_F16(accK[2*jj],   a, r0, r1);
                MMA_F16(accK[2*jj+1], a, r2, r3);
            }
        }
        __syncthreads();
    }

    __half* out = Qkh + (long)b*KTOK*DIM;
    #pragma unroll
    for (int j = 0; j < 4; ++j) {
        int n = n0 + nw*32 + j*8 + 2*(lane & 3);
        __half2 h01 = __floats2half2_rn(accK[j][0], accK[j][1]);
        __half2 h23 = __floats2half2_rn(accK[j][2], accK[j][3]);
        *(uint32_t*)(out + (long)mrow*DIM + n)     = *(uint32_t*)&h01;
        *(uint32_t*)(out + (long)(mrow+8)*DIM + n) = *(uint32_t*)&h23;
    }
}

// ===========================================================================
// tail_gemm<KIN,NCOLS> (unchanged — verified round 10).
// ===========================================================================
template<int KIN, int NCOLS>
__global__ __launch_bounds__(1024)
void tail_gemm(const float* __restrict__ Ag, const float* __restrict__ Wg,
               float* __restrict__ Cg)
{
    extern __shared__ __align__(16) unsigned char sm[];
    constexpr int PA     = KIN*2 + 16;
    constexpr int WOFF   = 64*PA;
    constexpr int WSTRIDE= 20480;
    constexpr int REDOFF = WOFF + 4*WSTRIDE;
    constexpr int KSTEPS = KIN/128;

    const int n0 = blockIdx.x * 128;
    const int b  = blockIdx.y;
    const int tid  = threadIdx.x;
    const int lane = tid & 31;
    const int warp = tid >> 5;
    const int wg    = warp >> 3;
    const int wwarp = warp & 7;
    const int mw = wwarp >> 2;
    const int nw = wwarp & 3;
    const int wtid = tid & 255;

    const float* Ab = Ag + (long)b*KTOK*KIN;

    #pragma unroll
    for (int p = 0; p < KIN/128; ++p) {
        int lin = tid + p*1024;
        int r  = lin / (KIN/4);
        int c4 = lin % (KIN/4);
        float4 v = *(const float4*)(Ab + r*KIN + 4*c4);
        uint2 hi, lo; cvt_split4h(v, hi, lo);
        *(uint2*)(sm + r*PA + 8*c4)         = hi;
        *(uint2*)(sm + 32*PA + r*PA + 8*c4) = lo;
    }

    const int kbase = wg * (KIN/4);
    const uint32_t smb = cvta_s(sm);
    const uint32_t aH = smb + (mw*16 + (lane & 15))*PA + (lane >> 4)*16 + kbase*2;
    const uint32_t aL = aH + 32*PA;
    const uint32_t wbase = smb + WOFF + wg*WSTRIDE;
    uint32_t bH[2];
    #pragma unroll
    for (int jj = 0; jj < 2; ++jj)
        bH[jj] = wbase + (nw*32 + jj*16 + (lane & 7) + ((lane >> 4) & 1)*8)*80
               + ((lane >> 3) & 1)*16;

    float4 pw[4];
    #pragma unroll
    for (int p = 0; p < 4; ++p) {
        int lin = wtid + p*256;
        pw[p] = *(const float4*)(Wg + (long)(n0 + (lin >> 3))*KIN + kbase + 4*(lin & 7));
    }

    float acc[4][4];
    #pragma unroll
    for (int j = 0; j < 4; ++j)
        #pragma unroll
        for (int r = 0; r < 4; ++r) acc[j][r] = 0.f;

    __syncthreads();

    for (int step = 0; step < KSTEPS; ++step) {
        #pragma unroll
        for (int p = 0; p < 4; ++p) {
            int lin = wtid + p*256;
            uint2 hi, lo; cvt_split4h(pw[p], hi, lo);
            *(uint2*)(sm + WOFF + wg*WSTRIDE + (lin >> 3)*80 + 8*(lin & 7))         = hi;
            *(uint2*)(sm + WOFF + wg*WSTRIDE + 10240 + (lin >> 3)*80 + 8*(lin & 7)) = lo;
        }
        asm volatile("bar.sync %0, %1;" :: "r"(wg+1), "r"(256) : "memory");

        if (step + 1 < KSTEPS) {
            int kn = kbase + (step+1)*32;
            #pragma unroll
            for (int p = 0; p < 4; ++p) {
                int lin = wtid + p*256;
                pw[p] = *(const float4*)(Wg + (long)(n0 + (lin >> 3))*KIN + kn + 4*(lin & 7));
            }
        }

        #pragma unroll
        for (int kt = 0; kt < 2; ++kt) {
            uint32_t ah[4], al[4];
            LDSM4(ah[0],ah[1],ah[2],ah[3], aH + step*64 + kt*32);
            LDSM4(al[0],al[1],al[2],al[3], aL + step*64 + kt*32);
            uint32_t bh[4][2], bl[4][2];
            #pragma unroll
            for (int jj = 0; jj < 2; ++jj) {
                uint32_t r0,r1,r2,r3;
                LDSM4(r0,r1,r2,r3, bH[jj] + kt*32);
                bh[2*jj][0]=r0; bh[2*jj][1]=r1; bh[2*jj+1][0]=r2; bh[2*jj+1][1]=r3;
                LDSM4(r0,r1,r2,r3, bH[jj] + 10240 + kt*32);
                bl[2*jj][0]=r0; bl[2*jj][1]=r1; bl[2*jj+1][0]=r2; bl[2*jj+1][1]=r3;
            }
            #pragma unroll
            for (int j = 0; j < 4; ++j) {
                MMA_F16(acc[j], ah, bh[j][0], bh[j][1]);
                MMA_F16(acc[j], ah, bl[j][0], bl[j][1]);
                MMA_F16(acc[j], al, bh[j][0], bh[j][1]);
            }
        }
        asm volatile("bar.sync %0, %1;" :: "r"(wg+1), "r"(256) : "memory");
    }

    {
        float* red = (float*)(sm + REDOFF) + wg*4096;
        const int mrow = mw*16 + (lane >> 2);
        #pragma unroll
        for (int j = 0; j < 4; ++j) {
            int c = nw*32 + j*8 + 2*(lane & 3);
            *(float2*)(red + mrow*128 + c)     = make_float2(acc[j][0], acc[j][1]);
            *(float2*)(red + (mrow+8)*128 + c) = make_float2(acc[j][2], acc[j][3]);
        }
    }
    __syncthreads();

    {
        int e = tid * 4;
        int r = e >> 7, c = e & 127;
        const float* red = (const float*)(sm + REDOFF);
        float4 s = make_float4(0.f, 0.f, 0.f, 0.f);
        #pragma unroll
        for (int w = 0; w < 4; ++w) {
            float4 v = *(const float4*)(red + w*4096 + r*128 + c);
            s.x += v.x; s.y += v.y; s.z += v.z; s.w += v.w;
        }
        *(float4*)(Cg + ((long)b*KTOK + r)*NCOLS + n0 + c) = s;
    }
}

// ---------------------------------------------------------------------------
__global__ void normalize_rows(float* __restrict__ C)
{
    const int row = blockIdx.x;
    float* p = C + (long)row * DIM;
    const int t = threadIdx.x;
    float v[4]; float ss = 0.f;
    #pragma unroll
    for (int i = 0; i < 4; i++) { v[i] = p[t + i*128]; ss += v[i]*v[i]; }
    __shared__ float red[128];
    red[t] = ss; __syncthreads();
    #pragma unroll
    for (int s = 64; s > 0; s >>= 1) {
        if (t < s) red[t] += red[t+s];
        __syncthreads();
    }
    float inv = 1.f / (sqrtf(red[0]) + 1e-8f);
    #pragma unroll
    for (int i = 0; i < 4; i++) p[t + i*128] = v[i] * inv;
}

extern "C" void kernel_launch(void* const* d_in, const int* in_sizes, int n_in,
                              void* d_out, int out_size)
{
    const float* E  = (const float*)d_in[0];
    const float* T  = (const float*)d_in[1];
    const float* P  = (const float*)d_in[2];
    const float* Wq = (const float*)d_in[3];
    const float* Wk = (const float*)d_in[4];
    const float* Wv = (const float*)d_in[5];
    const float* Wo = (const float*)d_in[6];

    float* outF = (float*)d_out;
    float* outA = (float*)d_out + (long)BATCH*KTOK*DIM;

    float *pGp, *pG, *pF, *pRows;
    __half* pQkh;
    cudaGetSymbolAddress((void**)&pQkh,  g_Qkh);
    cudaGetSymbolAddress((void**)&pGp,   g_Gp);
    cudaGetSymbolAddress((void**)&pG,    g_G);
    cudaGetSymbolAddress((void**)&pF,    g_F);
    cudaGetSymbolAddress((void**)&pRows, g_rows);

    const int TF_SMEM = 64*(512*2+16) + 4*20480 + 65536;   // 214016
    const int TO_SMEM = 64*(256*2+16) + 4*20480 + 65536;   // 181248

    cudaFuncSetAttribute(fused_attn5,
        cudaFuncAttributeMaxDynamicSharedMemorySize, SMEM_FUSED);
    cudaFuncSetAttribute(tail_gemm<512,256>,
        cudaFuncAttributeMaxDynamicSharedMemorySize, TF_SMEM);
    cudaFuncSetAttribute(tail_gemm<256,512>,
        cudaFuncAttributeMaxDynamicSharedMemorySize, TO_SMEM);

    dim3 blk(256);

    // 1) Qk = (T @ Wq^T) @ Wk  (merged, fp16 out)
    proj_qk<<<dim3(4, BATCH), blk>>>(T, Wq, Wk, pQkh);

    // 2) FUSED (warp-specialized): expS/A(unnorm) + rowsum + G partials
    fused_attn5<<<dim3(SPLITS, BATCH), 512, SMEM_FUSED>>>(
        pQkh, E, P, outA, pGp, pRows);

    // 3) post: G reduce (256 blocks) + A row-scale (512 blocks)
    post_kernel<<<768, blk>>>(pGp, pG, pRows, outA);

    // 4) F = G @ Wv^T
    tail_gemm<512,256><<<dim3(2, BATCH), 1024, TF_SMEM>>>(pG, Wv, pF);

    // 5) out = F @ Wo^T
    tail_gemm<256,512><<<dim3(4, BATCH), 1024, TO_SMEM>>>(pF, Wo, outF);

    // 6) L2-normalize outF rows
    normalize_rows<<<BATCH*KTOK, 128>>>(outF);
}

// round 12
// speedup vs baseline: 1.0568x; 1.0568x over previous
#include <cuda_runtime.h>
#include <cuda_bf16.h>
#include <cuda_fp16.h>
#include <math.h>
#include <stdint.h>

// Problem constants
#define BATCH 16
#define NPATCH 4096
#define KTOK 32
#define DIM 512
#define DHEAD 256
#define SCALE_V 0.0625f   // 256^-0.5

#define SPLITS 16         // fused grid = 16 x 16 = 256 blocks, occ 2

// Scratch (no allocation allowed -> device globals)
__device__ __half g_Qkh [BATCH*KTOK*DIM];
__device__ float  g_Gp  [SPLITS*BATCH*KTOK*DIM];
__device__ float  g_G   [BATCH*KTOK*DIM];
__device__ float  g_F   [BATCH*KTOK*DHEAD];
__device__ float  g_rows[BATCH*KTOK*SPLITS];
// Pre-fragmented weights: Wv frags (n8=32 x k16=32), Wo frags (n8=64 x k16=16)
__device__ uint4  g_Wvf [32*32*32];   // 512 KB
__device__ uint4  g_Wof [64*16*32];   // 512 KB

// ---------------------------------------------------------------------------

#define LDSM4(R0,R1,R2,R3,ADDR) \
    asm volatile("ldmatrix.sync.aligned.m8n8.x4.shared.b16 {%0,%1,%2,%3}, [%4];" \
        : "=r"(R0),"=r"(R1),"=r"(R2),"=r"(R3) : "r"(ADDR))

#define LDSM4T(R0,R1,R2,R3,ADDR) \
    asm volatile("ldmatrix.sync.aligned.m8n8.x4.trans.shared.b16 {%0,%1,%2,%3}, [%4];" \
        : "=r"(R0),"=r"(R1),"=r"(R2),"=r"(R3) : "r"(ADDR))

#define MMA_F16(C,A,B0,B1) \
    asm volatile("mma.sync.aligned.m16n8k16.row.col.f32.f16.f16.f32 " \
        "{%0,%1,%2,%3},{%4,%5,%6,%7},{%8,%9},{%0,%1,%2,%3};" \
        : "+f"((C)[0]),"+f"((C)[1]),"+f"((C)[2]),"+f"((C)[3]) \
        : "r"((A)[0]),"r"((A)[1]),"r"((A)[2]),"r"((A)[3]),"r"(B0),"r"(B1))

__device__ __forceinline__ uint32_t cvta_s(const void* p) {
    return (uint32_t)__cvta_generic_to_shared(p);
}

__device__ __forceinline__ uint2 cvt_h4(float4 v) {
    __half2 h0 = __floats2half2_rn(v.x, v.y);
    __half2 h1 = __floats2half2_rn(v.z, v.w);
    uint2 r; r.x = *(uint32_t*)&h0; r.y = *(uint32_t*)&h1; return r;
}

// fp16 hi/lo split (effective precision ~2^-22)
__device__ __forceinline__ void cvt_split4h(float4 v, uint2 &hi, uint2 &lo) {
    __half2 h0 = __floats2half2_rn(v.x, v.y);
    __half2 h1 = __floats2half2_rn(v.z, v.w);
    float rx = v.x - __half2float(h0.x);
    float ry = v.y - __half2float(h0.y);
    float rz = v.z - __half2float(h1.x);
    float rw = v.w - __half2float(h1.y);
    __half2 l0 = __floats2half2_rn(rx, ry);
    __half2 l1 = __floats2half2_rn(rz, rw);
    hi.x = *(uint32_t*)&h0; hi.y = *(uint32_t*)&h1;
    lo.x = *(uint32_t*)&l0; lo.y = *(uint32_t*)&l1;
}

// ===========================================================================
// prep_wfrag: convert Wv [256,512] and Wo [512,256] into MMA B-fragment
// layout: Wf[(n8*K16 + k16)*32 + lane] = {hi_b0, hi_b1, lo_b0, lo_b1}
// where lane holds W[n8*8 + lane/4][k16*16 + (lane%4)*2 + {0,1}] (b0)
// and k+8 (b1). Matches mma.m16n8k16 row.col B fragment.
// 65536 threads: first 32768 -> Wv, rest -> Wo.
// ===========================================================================
__global__ __launch_bounds__(256)
void prep_wfrag(const float* __restrict__ Wv, const float* __restrict__ Wo,
                uint4* __restrict__ Wvf, uint4* __restrict__ Wof)
{
    int t = blockIdx.x*256 + threadIdx.x;
    const float* W;
    uint4* out;
    int KIN, n8, k16, lane;
    if (t < 32768) {
        lane = t & 31;
        int f = t >> 5;               // 0..1023
        k16 = f & 31; n8 = f >> 5;    // K16=32, n8 in [0,32)
        W = Wv; out = Wvf + (long)f*32 + lane; KIN = 512;
    } else {
        int t2 = t - 32768;
        lane = t2 & 31;
        int f = t2 >> 5;              // 0..1023
        k16 = f & 15; n8 = f >> 4;    // K16=16, n8 in [0,64)
        W = Wo; out = Wof + (long)f*32 + lane; KIN = 256;
    }
    int n = n8*8 + (lane >> 2);
    int k = k16*16 + (lane & 3)*2;
    float w00 = W[(long)n*KIN + k],     w01 = W[(long)n*KIN + k + 1];
    float w10 = W[(long)n*KIN + k + 8], w11 = W[(long)n*KIN + k + 9];
    __half2 h0 = __floats2half2_rn(w00, w01);
    __half2 h1 = __floats2half2_rn(w10, w11);
    __half2 l0 = __floats2half2_rn(w00 - __half2float(h0.x), w01 - __half2float(h0.y));
    __half2 l1 = __floats2half2_rn(w10 - __half2float(h1.x), w11 - __half2float(h1.y));
    uint4 r;
    r.x = *(uint32_t*)&h0; r.y = *(uint32_t*)&h1;
    r.z = *(uint32_t*)&l0; r.w = *(uint32_t*)&l1;
    *out = r;
}

// ===========================================================================
// tail_gemm2<KIN,NCOLS>: C[b][32, n0:n0+64] = A[b][32,KIN] @ W^T (fragments).
// 256 thr = 8 warps (2 m x 4 n), each warp owns 16m x 16n (2 n8 frags).
// A staged once to smem fp16 hi/lo; W read directly as fragments (no smem).
// fp16 hi/lo 3-MMA. No inner-loop barriers.
// ===========================================================================
template<int KIN, int NCOLS>
__global__ __launch_bounds__(256)
void tail_gemm2(const float* __restrict__ Ag, const uint4* __restrict__ Wf,
                float* __restrict__ Cg)
{
    extern __shared__ __align__(16) unsigned char sm[];
    constexpr int PA  = KIN*2 + 16;
    constexpr int K16 = KIN/16;
    constexpr int F4R = KIN/4;            // float4 per A row

    const int n0 = blockIdx.x * 64;
    const int b  = blockIdx.y;
    const int tid  = threadIdx.x;
    const int lane = tid & 31;
    const int warp = tid >> 5;
    const int mw = warp >> 2;
    const int nw = warp & 3;

    const float* Ab = Ag + (long)b*KTOK*KIN;

    // ---- stage A[32,KIN] -> fp16 hi/lo planes ----
    #pragma unroll
    for (int p = 0; p < 32*F4R/256; ++p) {
        int lin = tid + p*256;
        int r  = lin / F4R;
        int c4 = lin % F4R;
        float4 v = *(const float4*)(Ab + r*KIN + 4*c4);
        uint2 hi, lo; cvt_split4h(v, hi, lo);
        *(uint2*)(sm + r*PA + 8*c4)         = hi;
        *(uint2*)(sm + 32*PA + r*PA + 8*c4) = lo;
    }
    __syncthreads();

    const uint32_t smb = cvta_s(sm);
    const uint32_t aH = smb + (mw*16 + (lane & 15))*PA + (lane >> 4)*16;
    const uint32_t aL = aH + 32*PA;

    const int n8g = (n0 >> 3) + nw*2;     // this warp's first n8 frag
    const uint4* Wf0 = Wf + ((long)n8g*K16)*32 + lane;
    const uint4* Wf1 = Wf + ((long)(n8g+1)*K16)*32 + lane;

    float acc[2][4];
    #pragma unroll
    for (int j = 0; j < 2; ++j)
        #pragma unroll
        for (int r = 0; r < 4; ++r) acc[j][r] = 0.f;

    #pragma unroll 8
    for (int k16 = 0; k16 < K16; ++k16) {
        uint4 b0 = Wf0[k16*32];
        uint4 b1 = Wf1[k16*32];
        uint32_t ah[4], al[4];
        LDSM4(ah[0],ah[1],ah[2],ah[3], aH + k16*32);
        LDSM4(al[0],al[1],al[2],al[3], aL + k16*32);
        MMA_F16(acc[0], ah, b0.x, b0.y);
        MMA_F16(acc[0], ah, b0.z, b0.w);
        MMA_F16(acc[0], al, b0.x, b0.y);
        MMA_F16(acc[1], ah, b1.x, b1.y);
        MMA_F16(acc[1], ah, b1.z, b1.w);
        MMA_F16(acc[1], al, b1.x, b1.y);
    }

    // ---- epilogue (warps own disjoint tiles) ----
    const int mrow = mw*16 + (lane >> 2);
    #pragma unroll
    for (int j = 0; j < 2; ++j) {
        int n = n0 + nw*16 + j*8 + 2*(lane & 3);
        *(float2*)(Cg + ((long)b*KTOK + mrow)*NCOLS + n)
            = make_float2(acc[j][0], acc[j][1]);
        *(float2*)(Cg + ((long)b*KTOK + mrow + 8)*NCOLS + n)
            = make_float2(acc[j][2], acc[j][3]);
    }
}

// ===========================================================================
// FUSED attention kernel v4 (round-8/10 verified version, SPLITS=16, occ 2).
// ===========================================================================
#define QK_OFF   0
#define QK_PITCH 1040
#define E_OFF    33280
#define E_PITCH  1040
#define ES_OFF   99840
#define ES_PITCH 144
#define RED_OFF  104448
#define LP_OFF   104960
#define SMEM_FUSED 105984

__global__ __launch_bounds__(256, 2)
void fused_attn4(const __half* __restrict__ Qkh, const float* __restrict__ E,
                 const float* __restrict__ P, float* __restrict__ outA,
                 float* __restrict__ Gp, float* __restrict__ rows)
{
    extern __shared__ __align__(16) unsigned char sm[];
    const int sp = blockIdx.x;
    const int b  = blockIdx.y;
    const int tid  = threadIdx.x;
    const int lane = tid & 31;
    const int warp = tid >> 5;
    const int mw = warp >> 2;
    const int nw = warp & 3;

    const float*  Eb  = E   + (long)b*NPATCH*DIM;
    const __half* Qkb = Qkh + (long)b*KTOK*DIM;
    const float*  Pb  = P   + (long)b*NPATCH;
    float*        Ab  = outA + (long)b*KTOK*NPATCH;

    const int nbase = sp * (NPATCH/SPLITS);

    #pragma unroll
    for (int p = 0; p < 8; ++p) {
        int lin = tid + p*256;
        int r = lin >> 6, seg = lin & 63;
        uint4 v = *(const uint4*)(Qkb + r*DIM + seg*8);
        *(uint4*)(sm + QK_OFF + r*QK_PITCH + seg*16) = v;
    }
    {
        float pv = Pb[nbase + tid];
        ((float*)(sm + LP_OFF))[tid] = __logf(fminf(fmaxf(pv, 0.1f), 0.9f));
    }

    float accG[16][4];
    #pragma unroll
    for (int t2 = 0; t2 < 16; ++t2)
        #pragma unroll
        for (int r = 0; r < 4; ++r) accG[t2][r] = 0.f;
    float rsum0 = 0.f, rsum8 = 0.f;

    const uint32_t smb = cvta_s(sm);
    const uint32_t aQkBase = smb + QK_OFF + (mw*16 + (lane & 15))*QK_PITCH + (lane >> 4)*16;
    const uint32_t b1Base  = smb + E_OFF
        + (nw*16 + (lane & 7) + ((lane >> 4) & 1)*8)*E_PITCH + ((lane >> 3) & 1)*16;
    const uint32_t aEsBase = smb + ES_OFF + (mw*16 + (lane & 15))*ES_PITCH + (lane >> 4)*16;
    const uint32_t b2Base  = smb + E_OFF + (lane & 15)*E_PITCH + nw*256 + ((lane >> 4) & 1)*16;
    const float* LPs = (const float*)(sm + LP_OFF);

    for (int c = 0; c < 4; ++c) {
        const int n0 = nbase + c*64;
        __syncthreads();
        #pragma unroll 8
        for (int p = 0; p < 32; ++p) {
            int lin = tid + p*256;
            int r = lin >> 7, c4 = lin & 127;
            float4 v = *(const float4*)(Eb + (long)(n0 + r)*DIM + 4*c4);
            *(uint2*)(sm + E_OFF + r*E_PITCH + 8*c4) = cvt_h4(v);
        }
        __syncthreads();

        float sacc[2][4];
        #pragma unroll
        for (int j = 0; j < 2; ++j)
            #pragma unroll
            for (int r = 0; r < 4; ++r) sacc[j][r] = 0.f;
        #pragma unroll
        for (int ks = 0; ks < 32; ++ks) {
            uint32_t a[4], r0, r1, r2, r3;
            LDSM4(a[0],a[1],a[2],a[3], aQkBase + ks*32);
            LDSM4(r0,r1,r2,r3, b1Base + ks*32);
            MMA_F16(sacc[0], a, r0, r1);
            MMA_F16(sacc[1], a, r2, r3);
        }

        {
            const int mrow = mw*16 + (lane >> 2);
            #pragma unroll
            for (int j = 0; j < 2; ++j) {
                int nl = nw*16 + j*8 + 2*(lane & 3);
                int gn = n0 + nl;
                float lp0 = LPs[c*64 + nl];
                float lp1 = LPs[c*64 + nl + 1];
                float v0 = __expf(sacc[j][0]*SCALE_V + lp0);
                float v1 = __expf(sacc[j][1]*SCALE_V + lp1);
                float v2 = __expf(sacc[j][2]*SCALE_V + lp0);
                float v3 = __expf(sacc[j][3]*SCALE_V + lp1);
                rsum0 += v0 + v1; rsum8 += v2 + v3;
                *(float2*)(Ab + (long)mrow*NPATCH + gn)     = make_float2(v0, v1);
                *(float2*)(Ab + (long)(mrow+8)*NPATCH + gn) = make_float2(v2, v3);
                __half2 h01 = __floats2half2_rn(v0, v1);
                __half2 h23 = __floats2half2_rn(v2, v3);
                *(uint32_t*)(sm + ES_OFF + mrow*ES_PITCH + nl*2)     = *(uint32_t*)&h01;
                *(uint32_t*)(sm + ES_OFF + (mrow+8)*ES_PITCH + nl*2) = *(uint32_t*)&h23;
            }
        }
        __syncthreads();

        #pragma unroll
        for (int ks = 0; ks < 4; ++ks) {
            uint32_t a[4];
            LDSM4(a[0],a[1],a[2],a[3], aEsBase + ks*32);
            #pragma unroll
            for (int jt = 0; jt < 8; ++jt) {
                uint32_t r0, r1, r2, r3;
                LDSM4T(r0,r1,r2,r3, b2Base + ks*16*E_PITCH + jt*32);
                MMA_F16(accG[2*jt],   a, r0, r1);
                MMA_F16(accG[2*jt+1], a, r2, r3);
            }
        }
    }

    {
        float* Gpb = Gp + ((long)(b*SPLITS + sp)*KTOK)*DIM;
        const int mrow = mw*16 + (lane >> 2);
        #pragma unroll
        for (int t2 = 0; t2 < 16; ++t2) {
            int d = nw*128 + t2*8 + 2*(lane & 3);
            *(float2*)(Gpb + (long)mrow*DIM + d)     = make_float2(accG[t2][0], accG[t2][1]);
            *(float2*)(Gpb + (long)(mrow+8)*DIM + d) = make_float2(accG[t2][2], accG[t2][3]);
        }
    }

    rsum0 += __shfl_xor_sync(0xffffffffu, rsum0, 1);
    rsum0 += __shfl_xor_sync(0xffffffffu, rsum0, 2);
    rsum8 += __shfl_xor_sync(0xffffffffu, rsum8, 1);
    rsum8 += __shfl_xor_sync(0xffffffffu, rsum8, 2);
    {
        float (*srow)[4] = (float(*)[4])(sm + RED_OFF);
        __syncthreads();
        if ((lane & 3) == 0) {
            srow[mw*16 + (lane >> 2)][nw]     = rsum0;
            srow[mw*16 + 8 + (lane >> 2)][nw] = rsum8;
        }
        __syncthreads();
        if (tid < 32) {
            float s = srow[tid][0] + srow[tid][1] + srow[tid][2] + srow[tid][3];
            rows[(b*KTOK + tid)*SPLITS + sp] = s;
        }
    }
}

// ===========================================================================
// post kernel: blocks [0,256) reduce G partials; blocks [256,768) scale A rows.
// ===========================================================================
__global__ __launch_bounds__(256)
void post_kernel(const float* __restrict__ Gp, float* __restrict__ G,
                 const float* __restrict__ rows, float* __restrict__ A)
{
    if (blockIdx.x < 256) {
        int i = blockIdx.x*256 + threadIdx.x;
        int bb  = i >> 12;
        int rem = i & 4095;
        const float4* p = (const float4*)Gp + ((long)bb*SPLITS)*4096 + rem;
        float4 s = make_float4(0.f, 0.f, 0.f, 0.f);
        #pragma unroll
        for (int s2 = 0; s2 < SPLITS; ++s2) {
            float4 v = p[(long)s2*4096];
            s.x += v.x; s.y += v.y; s.z += v.z; s.w += v.w;
        }
        ((float4*)G)[i] = s;
    } else {
        int r = blockIdx.x - 256;
        float s = 0.f;
        #pragma unroll
        for (int c = 0; c < SPLITS; ++c) s += rows[r*SPLITS + c];
        float inv = 1.f / s;
        float4* pa = (float4*)(A + (long)r*NPATCH);
        #pragma unroll
        for (int q = 0; q < 4; ++q) {
            int idx = threadIdx.x + q*256;
            float4 v = pa[idx];
            v.x *= inv; v.y *= inv; v.z *= inv; v.w *= inv;
            pa[idx] = v;
        }
    }
}

// ===========================================================================
// proj_qk (unchanged — verified).
// ===========================================================================
#define PJ_T     0
#define PJ_W     2560
#define PJ_Q     23040
#define PJ_BYTES 39936
#define QS_PITCH 528

__global__ __launch_bounds__(256)
void proj_qk(const float* __restrict__ T, const float* __restrict__ Wq,
             const float* __restrict__ Wk, __half* __restrict__ Qkh)
{
    __shared__ __align__(16) unsigned char sm[PJ_BYTES];
    const int nb = blockIdx.x;
    const int b  = blockIdx.y;
    const int tid  = threadIdx.x;
    const int lane = tid & 31;
    const int warp = tid >> 5;
    const int mw = warp >> 2;
    const int nw = warp & 3;

    const float* Tb = T + (long)b*KTOK*DIM;

    float accQ[8][4];
    #pragma unroll
    for (int j = 0; j < 8; ++j)
        #pragma unroll
        for (int r = 0; r < 4; ++r) accQ[j][r] = 0.f;

    const uint32_t aT = cvta_s(sm + PJ_T)
        + (mw*16 + (lane & 15))*80 + (lane >> 4)*16;
    uint32_t bW[4];
    #pragma unroll
    for (int jj = 0; jj < 4; ++jj)
        bW[jj] = cvta_s(sm + PJ_W)
            + (nw*64 + jj*16 + (lane & 7) + ((lane >> 4) & 1)*8)*80
            + ((lane >> 3) & 1)*16;

    const int am = tid >> 3, ak4 = tid & 7;

    float4 pt, pw[8];
    pt = *(const float4*)(Tb + am*DIM + 4*ak4);
    #pragma unroll
    for (int p = 0; p < 8; ++p) {
        int lin = tid + p*256;
        pw[p] = *(const float4*)(Wq + (long)(lin >> 3)*DIM + 4*(lin & 7));
    }

    for (int k0 = 0; k0 < DIM; k0 += 32) {
        *(uint2*)(sm + PJ_T + am*80 + 8*ak4) = cvt_h4(pt);
        #pragma unroll
        for (int p = 0; p < 8; ++p) {
            int lin = tid + p*256;
            *(uint2*)(sm + PJ_W + (lin >> 3)*80 + 8*(lin & 7)) = cvt_h4(pw[p]);
        }
        __syncthreads();

        int kn = k0 + 32;
        if (kn < DIM) {
            pt = *(const float4*)(Tb + am*DIM + kn + 4*ak4);
            #pragma unroll
            for (int p = 0; p < 8; ++p) {
                int lin = tid + p*256;
                pw[p] = *(const float4*)(Wq + (long)(lin >> 3)*DIM + kn + 4*(lin & 7));
            }
        }

        #pragma unroll
        for (int kt = 0; kt < 2; ++kt) {
            uint32_t a[4];
            LDSM4(a[0],a[1],a[2],a[3], aT + kt*32);
            #pragma unroll
            for (int jj = 0; jj < 4; ++jj) {
                uint32_t r0,r1,r2,r3;
                LDSM4(r0,r1,r2,r3, bW[jj] + kt*32);
                MMA_F16(accQ[2*jj],   a, r0, r1);
                MMA_F16(accQ[2*jj+1], a, r2, r3);
            }
        }
        __syncthreads();
    }

    const int mrow = mw*16 + (lane >> 2);
    #pragma unroll
    for (int j = 0; j < 8; ++j) {
        int col = nw*64 + j*8 + 2*(lane & 3);
        __half2 h01 = __floats2half2_rn(accQ[j][0], accQ[j][1]);
        __half2 h23 = __floats2half2_rn(accQ[j][2], accQ[j][3]);
        *(uint32_t*)(sm + PJ_Q + mrow*QS_PITCH + col*2)     = *(uint32_t*)&h01;
        *(uint32_t*)(sm + PJ_Q + (mrow+8)*QS_PITCH + col*2) = *(uint32_t*)&h23;
    }
    __syncthreads();

    float accK[4][4];
    #pragma unroll
    for (int j = 0; j < 4; ++j)
        #pragma unroll
        for (int r = 0; r < 4; ++r) accK[j][r] = 0.f;

    const uint32_t aQ = cvta_s(sm + PJ_Q)
        + (mw*16 + (lane & 15))*QS_PITCH + (lane >> 4)*16;
    uint32_t bK[2];
    #pragma unroll
    for (int jj = 0; jj < 2; ++jj)
        bK[jj] = cvta_s(sm + PJ_W) + (lane & 15)*272
            + (nw*32 + jj*16)*2 + ((lane >> 4) & 1)*16;

    const int n0 = nb*128;
    float4 pk[4];
    #pragma unroll
    for (int p = 0; p < 4; ++p) {
        int lin = tid + p*256;
        pk[p] = *(const float4*)(Wk + (long)(lin >> 5)*DIM + n0 + 4*(lin & 31));
    }

    for (int k0 = 0; k0 < DHEAD; k0 += 32) {
        #pragma unroll
        for (int p = 0; p < 4; ++p) {
            int lin = tid + p*256;
            *(uint2*)(sm + PJ_W + (lin >> 5)*272 + 8*(lin & 31)) = cvt_h4(pk[p]);
        }
        __syncthreads();

        int kn = k0 + 32;
        if (kn < DHEAD) {
            #pragma unroll
            for (int p = 0; p < 4; ++p) {
                int lin = tid + p*256;
                pk[p] = *(const float4*)(Wk + (long)(kn + (lin >> 5))*DIM + n0 + 4*(lin & 31));
            }
        }

        #pragma unroll
        for (int kt = 0; kt < 2; ++kt) {
            uint32_t a[4];
            LDSM4(a[0],a[1],a[2],a[3], aQ + k0*2 + kt*32);
            #pragma unroll
            for (int jj = 0; jj < 2; ++jj) {
                uint32_t r0,r1,r2,r3;
                LDSM4T(r0,r1,r2,r3, bK[jj] + kt*16*272);
                MMA_F16(accK[2*jj],   a, r0, r1);
                MMA_F16(accK[2*jj+1], a, r2, r3);
            }
        }
        __syncthreads();
    }

    __half* out = Qkh + (long)b*KTOK*DIM;
    #pragma unroll
    for (int j = 0; j < 4; ++j) {
        int n = n0 + nw*32 + j*8 + 2*(lane & 3);
        __half2 h01 = __floats2half2_rn(accK[j][0], accK[j][1]);
        __half2 h23 = __floats2half2_rn(accK[j][2], accK[j][3]);
        *(uint32_t*)(out + (long)mrow*DIM + n)     = *(uint32_t*)&h01;
        *(uint32_t*)(out + (long)(mrow+8)*DIM + n) = *(uint32_t*)&h23;
    }
}

// ---------------------------------------------------------------------------
__global__ void normalize_rows(float* __restrict__ C)
{
    const int row = blockIdx.x;
    float* p = C + (long)row * DIM;
    const int t = threadIdx.x;
    float v[4]; float ss = 0.f;
    #pragma unroll
    for (int i = 0; i < 4; i++) { v[i] = p[t + i*128]; ss += v[i]*v[i]; }
    __shared__ float red[128];
    red[t] = ss; __syncthreads();
    #pragma unroll
    for (int s = 64; s > 0; s >>= 1) {
        if (t < s) red[t] += red[t+s];
        __syncthreads();
    }
    float inv = 1.f / (sqrtf(red[0]) + 1e-8f);
    #pragma unroll
    for (int i = 0; i < 4; i++) p[t + i*128] = v[i] * inv;
}

extern "C" void kernel_launch(void* const* d_in, const int* in_sizes, int n_in,
                              void* d_out, int out_size)
{
    const float* E  = (const float*)d_in[0];
    const float* T  = (const float*)d_in[1];
    const float* P  = (const float*)d_in[2];
    const float* Wq = (const float*)d_in[3];
    const float* Wk = (const float*)d_in[4];
    const float* Wv = (const float*)d_in[5];
    const float* Wo = (const float*)d_in[6];

    float* outF = (float*)d_out;
    float* outA = (float*)d_out + (long)BATCH*KTOK*DIM;

    float *pGp, *pG, *pF, *pRows;
    __half* pQkh;
    uint4 *pWvf, *pWof;
    cudaGetSymbolAddress((void**)&pQkh,  g_Qkh);
    cudaGetSymbolAddress((void**)&pGp,   g_Gp);
    cudaGetSymbolAddress((void**)&pG,    g_G);
    cudaGetSymbolAddress((void**)&pF,    g_F);
    cudaGetSymbolAddress((void**)&pRows, g_rows);
    cudaGetSymbolAddress((void**)&pWvf,  g_Wvf);
    cudaGetSymbolAddress((void**)&pWof,  g_Wof);

    const int TF_SMEM = 64*(512*2+16);   // 66560
    const int TO_SMEM = 64*(256*2+16);   // 33792

    cudaFuncSetAttribute(fused_attn4,
        cudaFuncAttributeMaxDynamicSharedMemorySize, SMEM_FUSED);
    cudaFuncSetAttribute(tail_gemm2<512,256>,
        cudaFuncAttributeMaxDynamicSharedMemorySize, TF_SMEM);
    cudaFuncSetAttribute(tail_gemm2<256,512>,
        cudaFuncAttributeMaxDynamicSharedMemorySize, TO_SMEM);

    dim3 blk(256);

    // 0) weight fragment prep (no dependencies)
    prep_wfrag<<<256, blk>>>(Wv, Wo, pWvf, pWof);

    // 1) Qk = (T @ Wq^T) @ Wk  (merged, fp16 out)
    proj_qk<<<dim3(4, BATCH), blk>>>(T, Wq, Wk, pQkh);

    // 2) FUSED: expS/A(unnorm) + row-sum partials + G partials
    fused_attn4<<<dim3(SPLITS, BATCH), blk, SMEM_FUSED>>>(
        pQkh, E, P, outA, pGp, pRows);

    // 3) post: G reduce (256 blocks) + A row-scale (512 blocks)
    post_kernel<<<768, blk>>>(pGp, pG, pRows, outA);

    // 4) F = G @ Wv^T  (fragment-direct, 64 blocks)
    tail_gemm2<512,256><<<dim3(4, BATCH), blk, TF_SMEM>>>(pG, pWvf, pF);

    // 5) out = F @ Wo^T  (fragment-direct, 128 blocks)
    tail_gemm2<256,512><<<dim3(8, BATCH), blk, TO_SMEM>>>(pF, pWof, outF);

    // 6) L2-normalize outF rows
    normalize_rows<<<BATCH*KTOK, 128>>>(outF);
}

// round 13
// speedup vs baseline: 1.1471x; 1.0854x over previous
#include <cuda_runtime.h>
#include <cuda_bf16.h>
#include <cuda_fp16.h>
#include <math.h>
#include <stdint.h>

// Problem constants
#define BATCH 16
#define NPATCH 4096
#define KTOK 32
#define DIM 512
#define DHEAD 256
#define SCALE_V 0.0625f   // 256^-0.5

#define SPLITS 16         // fused grid = 16 x 16 = 256 blocks, occ 2
#define NBLK_MT 256       // mega_tail blocks (must all be co-resident)

// Scratch (no allocation allowed -> device globals)
__device__ __half g_Qkh [BATCH*KTOK*DIM];
__device__ float  g_Gp  [SPLITS*BATCH*KTOK*DIM];
__device__ float  g_G   [BATCH*KTOK*DIM];
__device__ float  g_F   [BATCH*KTOK*DHEAD];
__device__ float  g_rows[BATCH*KTOK*SPLITS];
__device__ uint4  g_Wvf [32*32*32];   // Wv fragments
__device__ uint4  g_Wof [64*16*32];   // Wo fragments
__device__ unsigned g_barcnt;
__device__ unsigned g_bargen;

// ---------------------------------------------------------------------------

#define LDSM4(R0,R1,R2,R3,ADDR) \
    asm volatile("ldmatrix.sync.aligned.m8n8.x4.shared.b16 {%0,%1,%2,%3}, [%4];" \
        : "=r"(R0),"=r"(R1),"=r"(R2),"=r"(R3) : "r"(ADDR))

#define LDSM4T(R0,R1,R2,R3,ADDR) \
    asm volatile("ldmatrix.sync.aligned.m8n8.x4.trans.shared.b16 {%0,%1,%2,%3}, [%4];" \
        : "=r"(R0),"=r"(R1),"=r"(R2),"=r"(R3) : "r"(ADDR))

#define MMA_F16(C,A,B0,B1) \
    asm volatile("mma.sync.aligned.m16n8k16.row.col.f32.f16.f16.f32 " \
        "{%0,%1,%2,%3},{%4,%5,%6,%7},{%8,%9},{%0,%1,%2,%3};" \
        : "+f"((C)[0]),"+f"((C)[1]),"+f"((C)[2]),"+f"((C)[3]) \
        : "r"((A)[0]),"r"((A)[1]),"r"((A)[2]),"r"((A)[3]),"r"(B0),"r"(B1))

__device__ __forceinline__ uint32_t cvta_s(const void* p) {
    return (uint32_t)__cvta_generic_to_shared(p);
}

__device__ __forceinline__ uint2 cvt_h4(float4 v) {
    __half2 h0 = __floats2half2_rn(v.x, v.y);
    __half2 h1 = __floats2half2_rn(v.z, v.w);
    uint2 r; r.x = *(uint32_t*)&h0; r.y = *(uint32_t*)&h1; return r;
}

__device__ __forceinline__ void cvt_split4h(float4 v, uint2 &hi, uint2 &lo) {
    __half2 h0 = __floats2half2_rn(v.x, v.y);
    __half2 h1 = __floats2half2_rn(v.z, v.w);
    float rx = v.x - __half2float(h0.x);
    float ry = v.y - __half2float(h0.y);
    float rz = v.z - __half2float(h1.x);
    float rw = v.w - __half2float(h1.y);
    __half2 l0 = __floats2half2_rn(rx, ry);
    __half2 l1 = __floats2half2_rn(rz, rw);
    hi.x = *(uint32_t*)&h0; hi.y = *(uint32_t*)&h1;
    lo.x = *(uint32_t*)&l0; lo.y = *(uint32_t*)&l1;
}

// Grid-wide barrier for mega_tail (all NBLK_MT blocks co-resident: occ 2).
__device__ __forceinline__ void grid_barrier() {
    __syncthreads();
    if (threadIdx.x == 0) {
        __threadfence();
        unsigned gen = atomicAdd(&g_bargen, 0u);
        if (atomicAdd(&g_barcnt, 1u) == NBLK_MT - 1u) {
            atomicExch(&g_barcnt, 0u);
            __threadfence();
            atomicAdd(&g_bargen, 1u);
        } else {
            while (atomicAdd(&g_bargen, 0u) == gen) { __nanosleep(64); }
        }
    }
    __syncthreads();
}

// ===========================================================================
// prep_proj: blocks [0,256) build W fragments; blocks [256,320) run proj_qk.
// ===========================================================================
#define PJ_T     0
#define PJ_W     2560
#define PJ_Q     23040
#define PJ_BYTES 39936
#define QS_PITCH 528

__global__ __launch_bounds__(256)
void prep_proj(const float* __restrict__ T, const float* __restrict__ Wq,
               const float* __restrict__ Wk, const float* __restrict__ Wv,
               const float* __restrict__ Wo, __half* __restrict__ Qkh,
               uint4* __restrict__ Wvf, uint4* __restrict__ Wof)
{
    __shared__ __align__(16) unsigned char sm[PJ_BYTES];

    if (blockIdx.x < 256) {
        // ---- weight fragment prep ----
        int t = blockIdx.x*256 + threadIdx.x;
        const float* W;
        uint4* out;
        int KIN, n8, k16, lane;
        if (t < 32768) {
            lane = t & 31;
            int f = t >> 5;
            k16 = f & 31; n8 = f >> 5;
            W = Wv; out = Wvf + (long)f*32 + lane; KIN = 512;
        } else {
            int t2 = t - 32768;
            lane = t2 & 31;
            int f = t2 >> 5;
            k16 = f & 15; n8 = f >> 4;
            W = Wo; out = Wof + (long)f*32 + lane; KIN = 256;
        }
        int n = n8*8 + (lane >> 2);
        int k = k16*16 + (lane & 3)*2;
        float w00 = W[(long)n*KIN + k],     w01 = W[(long)n*KIN + k + 1];
        float w10 = W[(long)n*KIN + k + 8], w11 = W[(long)n*KIN + k + 9];
        __half2 h0 = __floats2half2_rn(w00, w01);
        __half2 h1 = __floats2half2_rn(w10, w11);
        __half2 l0 = __floats2half2_rn(w00 - __half2float(h0.x), w01 - __half2float(h0.y));
        __half2 l1 = __floats2half2_rn(w10 - __half2float(h1.x), w11 - __half2float(h1.y));
        uint4 r;
        r.x = *(uint32_t*)&h0; r.y = *(uint32_t*)&h1;
        r.z = *(uint32_t*)&l0; r.w = *(uint32_t*)&l1;
        *out = r;
        return;
    }

    // ---- proj_qk (verified body) ----
    const int pb = blockIdx.x - 256;     // 0..63
    const int nb = pb & 3;
    const int b  = pb >> 2;
    const int tid  = threadIdx.x;
    const int lane = tid & 31;
    const int warp = tid >> 5;
    const int mw = warp >> 2;
    const int nw = warp & 3;

    const float* Tb = T + (long)b*KTOK*DIM;

    float accQ[8][4];
    #pragma unroll
    for (int j = 0; j < 8; ++j)
        #pragma unroll
        for (int r = 0; r < 4; ++r) accQ[j][r] = 0.f;

    const uint32_t aT = cvta_s(sm + PJ_T)
        + (mw*16 + (lane & 15))*80 + (lane >> 4)*16;
    uint32_t bW[4];
    #pragma unroll
    for (int jj = 0; jj < 4; ++jj)
        bW[jj] = cvta_s(sm + PJ_W)
            + (nw*64 + jj*16 + (lane & 7) + ((lane >> 4) & 1)*8)*80
            + ((lane >> 3) & 1)*16;

    const int am = tid >> 3, ak4 = tid & 7;

    float4 pt, pw[8];
    pt = *(const float4*)(Tb + am*DIM + 4*ak4);
    #pragma unroll
    for (int p = 0; p < 8; ++p) {
        int lin = tid + p*256;
        pw[p] = *(const float4*)(Wq + (long)(lin >> 3)*DIM + 4*(lin & 7));
    }

    for (int k0 = 0; k0 < DIM; k0 += 32) {
        *(uint2*)(sm + PJ_T + am*80 + 8*ak4) = cvt_h4(pt);
        #pragma unroll
        for (int p = 0; p < 8; ++p) {
            int lin = tid + p*256;
            *(uint2*)(sm + PJ_W + (lin >> 3)*80 + 8*(lin & 7)) = cvt_h4(pw[p]);
        }
        __syncthreads();

        int kn = k0 + 32;
        if (kn < DIM) {
            pt = *(const float4*)(Tb + am*DIM + kn + 4*ak4);
            #pragma unroll
            for (int p = 0; p < 8; ++p) {
                int lin = tid + p*256;
                pw[p] = *(const float4*)(Wq + (long)(lin >> 3)*DIM + kn + 4*(lin & 7));
            }
        }

        #pragma unroll
        for (int kt = 0; kt < 2; ++kt) {
            uint32_t a[4];
            LDSM4(a[0],a[1],a[2],a[3], aT + kt*32);
            #pragma unroll
            for (int jj = 0; jj < 4; ++jj) {
                uint32_t r0,r1,r2,r3;
                LDSM4(r0,r1,r2,r3, bW[jj] + kt*32);
                MMA_F16(accQ[2*jj],   a, r0, r1);
                MMA_F16(accQ[2*jj+1], a, r2, r3);
            }
        }
        __syncthreads();
    }

    const int mrow = mw*16 + (lane >> 2);
    #pragma unroll
    for (int j = 0; j < 8; ++j) {
        int col = nw*64 + j*8 + 2*(lane & 3);
        __half2 h01 = __floats2half2_rn(accQ[j][0], accQ[j][1]);
        __half2 h23 = __floats2half2_rn(accQ[j][2], accQ[j][3]);
        *(uint32_t*)(sm + PJ_Q + mrow*QS_PITCH + col*2)     = *(uint32_t*)&h01;
        *(uint32_t*)(sm + PJ_Q + (mrow+8)*QS_PITCH + col*2) = *(uint32_t*)&h23;
    }
    __syncthreads();

    float accK[4][4];
    #pragma unroll
    for (int j = 0; j < 4; ++j)
        #pragma unroll
        for (int r = 0; r < 4; ++r) accK[j][r] = 0.f;

    const uint32_t aQ = cvta_s(sm + PJ_Q)
        + (mw*16 + (lane & 15))*QS_PITCH + (lane >> 4)*16;
    uint32_t bK[2];
    #pragma unroll
    for (int jj = 0; jj < 2; ++jj)
        bK[jj] = cvta_s(sm + PJ_W) + (lane & 15)*272
            + (nw*32 + jj*16)*2 + ((lane >> 4) & 1)*16;

    const int n0 = nb*128;
    float4 pk[4];
    #pragma unroll
    for (int p = 0; p < 4; ++p) {
        int lin = tid + p*256;
        pk[p] = *(const float4*)(Wk + (long)(lin >> 5)*DIM + n0 + 4*(lin & 31));
    }

    for (int k0 = 0; k0 < DHEAD; k0 += 32) {
        #pragma unroll
        for (int p = 0; p < 4; ++p) {
            int lin = tid + p*256;
            *(uint2*)(sm + PJ_W + (lin >> 5)*272 + 8*(lin & 31)) = cvt_h4(pk[p]);
        }
        __syncthreads();

        int kn = k0 + 32;
        if (kn < DHEAD) {
            #pragma unroll
            for (int p = 0; p < 4; ++p) {
                int lin = tid + p*256;
                pk[p] = *(const float4*)(Wk + (long)(kn + (lin >> 5))*DIM + n0 + 4*(lin & 31));
            }
        }

        #pragma unroll
        for (int kt = 0; kt < 2; ++kt) {
            uint32_t a[4];
            LDSM4(a[0],a[1],a[2],a[3], aQ + k0*2 + kt*32);
            #pragma unroll
            for (int jj = 0; jj < 2; ++jj) {
                uint32_t r0,r1,r2,r3;
                LDSM4T(r0,r1,r2,r3, bK[jj] + kt*16*272);
                MMA_F16(accK[2*jj],   a, r0, r1);
                MMA_F16(accK[2*jj+1], a, r2, r3);
            }
        }
        __syncthreads();
    }

    __half* out = Qkh + (long)b*KTOK*DIM;
    #pragma unroll
    for (int j = 0; j < 4; ++j) {
        int n = n0 + nw*32 + j*8 + 2*(lane & 3);
        __half2 h01 = __floats2half2_rn(accK[j][0], accK[j][1]);
        __half2 h23 = __floats2half2_rn(accK[j][2], accK[j][3]);
        *(uint32_t*)(out + (long)mrow*DIM + n)     = *(uint32_t*)&h01;
        *(uint32_t*)(out + (long)(mrow+8)*DIM + n) = *(uint32_t*)&h23;
    }
}

// ===========================================================================
// FUSED attention kernel v4 (verified, unchanged).
// ===========================================================================
#define QK_OFF   0
#define QK_PITCH 1040
#define E_OFF    33280
#define E_PITCH  1040
#define ES_OFF   99840
#define ES_PITCH 144
#define RED_OFF  104448
#define LP_OFF   104960
#define SMEM_FUSED 105984

__global__ __launch_bounds__(256, 2)
void fused_attn4(const __half* __restrict__ Qkh, const float* __restrict__ E,
                 const float* __restrict__ P, float* __restrict__ outA,
                 float* __restrict__ Gp, float* __restrict__ rows)
{
    extern __shared__ __align__(16) unsigned char sm[];
    const int sp = blockIdx.x;
    const int b  = blockIdx.y;
    const int tid  = threadIdx.x;
    const int lane = tid & 31;
    const int warp = tid >> 5;
    const int mw = warp >> 2;
    const int nw = warp & 3;

    const float*  Eb  = E   + (long)b*NPATCH*DIM;
    const __half* Qkb = Qkh + (long)b*KTOK*DIM;
    const float*  Pb  = P   + (long)b*NPATCH;
    float*        Ab  = outA + (long)b*KTOK*NPATCH;

    const int nbase = sp * (NPATCH/SPLITS);

    #pragma unroll
    for (int p = 0; p < 8; ++p) {
        int lin = tid + p*256;
        int r = lin >> 6, seg = lin & 63;
        uint4 v = *(const uint4*)(Qkb + r*DIM + seg*8);
        *(uint4*)(sm + QK_OFF + r*QK_PITCH + seg*16) = v;
    }
    {
        float pv = Pb[nbase + tid];
        ((float*)(sm + LP_OFF))[tid] = __logf(fminf(fmaxf(pv, 0.1f), 0.9f));
    }

    float accG[16][4];
    #pragma unroll
    for (int t2 = 0; t2 < 16; ++t2)
        #pragma unroll
        for (int r = 0; r < 4; ++r) accG[t2][r] = 0.f;
    float rsum0 = 0.f, rsum8 = 0.f;

    const uint32_t smb = cvta_s(sm);
    const uint32_t aQkBase = smb + QK_OFF + (mw*16 + (lane & 15))*QK_PITCH + (lane >> 4)*16;
    const uint32_t b1Base  = smb + E_OFF
        + (nw*16 + (lane & 7) + ((lane >> 4) & 1)*8)*E_PITCH + ((lane >> 3) & 1)*16;
    const uint32_t aEsBase = smb + ES_OFF + (mw*16 + (lane & 15))*ES_PITCH + (lane >> 4)*16;
    const uint32_t b2Base  = smb + E_OFF + (lane & 15)*E_PITCH + nw*256 + ((lane >> 4) & 1)*16;
    const float* LPs = (const float*)(sm + LP_OFF);

    for (int c = 0; c < 4; ++c) {
        const int n0 = nbase + c*64;
        __syncthreads();
        #pragma unroll 8
        for (int p = 0; p < 32; ++p) {
            int lin = tid + p*256;
            int r = lin >> 7, c4 = lin & 127;
            float4 v = *(const float4*)(Eb + (long)(n0 + r)*DIM + 4*c4);
            *(uint2*)(sm + E_OFF + r*E_PITCH + 8*c4) = cvt_h4(v);
        }
        __syncthreads();

        float sacc[2][4];
        #pragma unroll
        for (int j = 0; j < 2; ++j)
            #pragma unroll
            for (int r = 0; r < 4; ++r) sacc[j][r] = 0.f;
        #pragma unroll
        for (int ks = 0; ks < 32; ++ks) {
            uint32_t a[4], r0, r1, r2, r3;
            LDSM4(a[0],a[1],a[2],a[3], aQkBase + ks*32);
            LDSM4(r0,r1,r2,r3, b1Base + ks*32);
            MMA_F16(sacc[0], a, r0, r1);
            MMA_F16(sacc[1], a, r2, r3);
        }

        {
            const int mrow = mw*16 + (lane >> 2);
            #pragma unroll
            for (int j = 0; j < 2; ++j) {
                int nl = nw*16 + j*8 + 2*(lane & 3);
                int gn = n0 + nl;
                float lp0 = LPs[c*64 + nl];
                float lp1 = LPs[c*64 + nl + 1];
                float v0 = __expf(sacc[j][0]*SCALE_V + lp0);
                float v1 = __expf(sacc[j][1]*SCALE_V + lp1);
                float v2 = __expf(sacc[j][2]*SCALE_V + lp0);
                float v3 = __expf(sacc[j][3]*SCALE_V + lp1);
                rsum0 += v0 + v1; rsum8 += v2 + v3;
                *(float2*)(Ab + (long)mrow*NPATCH + gn)     = make_float2(v0, v1);
                *(float2*)(Ab + (long)(mrow+8)*NPATCH + gn) = make_float2(v2, v3);
                __half2 h01 = __floats2half2_rn(v0, v1);
                __half2 h23 = __floats2half2_rn(v2, v3);
                *(uint32_t*)(sm + ES_OFF + mrow*ES_PITCH + nl*2)     = *(uint32_t*)&h01;
                *(uint32_t*)(sm + ES_OFF + (mrow+8)*ES_PITCH + nl*2) = *(uint32_t*)&h23;
            }
        }
        __syncthreads();

        #pragma unroll
        for (int ks = 0; ks < 4; ++ks) {
            uint32_t a[4];
            LDSM4(a[0],a[1],a[2],a[3], aEsBase + ks*32);
            #pragma unroll
            for (int jt = 0; jt < 8; ++jt) {
                uint32_t r0, r1, r2, r3;
                LDSM4T(r0,r1,r2,r3, b2Base + ks*16*E_PITCH + jt*32);
                MMA_F16(accG[2*jt],   a, r0, r1);
                MMA_F16(accG[2*jt+1], a, r2, r3);
            }
        }
    }

    {
        float* Gpb = Gp + ((long)(b*SPLITS + sp)*KTOK)*DIM;
        const int mrow = mw*16 + (lane >> 2);
        #pragma unroll
        for (int t2 = 0; t2 < 16; ++t2) {
            int d = nw*128 + t2*8 + 2*(lane & 3);
            *(float2*)(Gpb + (long)mrow*DIM + d)     = make_float2(accG[t2][0], accG[t2][1]);
            *(float2*)(Gpb + (long)(mrow+8)*DIM + d) = make_float2(accG[t2][2], accG[t2][3]);
        }
    }

    rsum0 += __shfl_xor_sync(0xffffffffu, rsum0, 1);
    rsum0 += __shfl_xor_sync(0xffffffffu, rsum0, 2);
    rsum8 += __shfl_xor_sync(0xffffffffu, rsum8, 1);
    rsum8 += __shfl_xor_sync(0xffffffffu, rsum8, 2);
    {
        float (*srow)[4] = (float(*)[4])(sm + RED_OFF);
        __syncthreads();
        if ((lane & 3) == 0) {
            srow[mw*16 + (lane >> 2)][nw]     = rsum0;
            srow[mw*16 + 8 + (lane >> 2)][nw] = rsum8;
        }
        __syncthreads();
        if (tid < 32) {
            float s = srow[tid][0] + srow[tid][1] + srow[tid][2] + srow[tid][3];
            rows[(b*KTOK + tid)*SPLITS + sp] = s;
        }
    }
}

// ===========================================================================
// mega_tail: 256 blocks x 256 thr, occ 2 (all co-resident).
//   stage 1: G-reduce (1 float4/thread) + A-rescale (2 rows/block)
//   barrier
//   stage 2 (blocks<64):  F = G @ Wv^T  (fragment-direct)
//   barrier
//   stage 3 (blocks<128): outF = F @ Wo^T (fragment-direct)
//   barrier
//   stage 4: L2-normalize (2 rows/block)
// ===========================================================================
__global__ __launch_bounds__(256, 2)
void mega_tail(const float* __restrict__ Gp, float* __restrict__ G,
               const float* __restrict__ rows, float* __restrict__ A,
               const uint4* __restrict__ Wvf, const uint4* __restrict__ Wof,
               float* __restrict__ F, float* __restrict__ outF)
{
    extern __shared__ __align__(16) unsigned char sm[];
    const int bid  = blockIdx.x;
    const int tid  = threadIdx.x;
    const int lane = tid & 31;
    const int warp = tid >> 5;
    const int mw = warp >> 2;
    const int nw = warp & 3;
    const uint32_t smb = cvta_s(sm);

    // ---------- stage 1a: G reduce ----------
    {
        int i = bid*256 + tid;               // 65536 float4
        int bb  = i >> 12;
        int rem = i & 4095;
        const float4* p = (const float4*)Gp + ((long)bb*SPLITS)*4096 + rem;
        float4 s = make_float4(0.f, 0.f, 0.f, 0.f);
        #pragma unroll
        for (int s2 = 0; s2 < SPLITS; ++s2) {
            float4 v = p[(long)s2*4096];
            s.x += v.x; s.y += v.y; s.z += v.z; s.w += v.w;
        }
        ((float4*)G)[i] = s;
    }
    // ---------- stage 1b: A rescale (rows 2*bid, 2*bid+1) ----------
    {
        float* sinv = (float*)sm;
        if (tid < 2) {
            int r = bid*2 + tid;
            float s = 0.f;
            #pragma unroll
            for (int c = 0; c < SPLITS; ++c) s += rows[r*SPLITS + c];
            sinv[tid] = 1.f / s;
        }
        __syncthreads();
        float4* pa = (float4*)(A + (long)(bid*2)*NPATCH);
        #pragma unroll
        for (int q = 0; q < 8; ++q) {
            int idx = tid + q*256;           // 2048 float4 = 2 rows
            float s = sinv[idx >> 10];
            float4 v = pa[idx];
            v.x *= s; v.y *= s; v.z *= s; v.w *= s;
            pa[idx] = v;
        }
    }

    grid_barrier();

    // ---------- stage 2: F = G @ Wv^T (blocks < 64) ----------
    if (bid < 64) {
        constexpr int KIN = 512, NCOLS = 256, PA = KIN*2 + 16, K16 = KIN/16, F4R = KIN/4;
        const int n0 = (bid & 3) * 64;
        const int b  = bid >> 2;
        const float* Ab = G + (long)b*KTOK*KIN;

        #pragma unroll
        for (int p = 0; p < 32*F4R/256; ++p) {
            int lin = tid + p*256;
            int r  = lin / F4R;
            int c4 = lin % F4R;
            float4 v = *(const float4*)(Ab + r*KIN + 4*c4);
            uint2 hi, lo; cvt_split4h(v, hi, lo);
            *(uint2*)(sm + r*PA + 8*c4)         = hi;
            *(uint2*)(sm + 32*PA + r*PA + 8*c4) = lo;
        }
        __syncthreads();

        const uint32_t aH = smb + (mw*16 + (lane & 15))*PA + (lane >> 4)*16;
        const uint32_t aL = aH + 32*PA;
        const int n8g = (n0 >> 3) + nw*2;
        const uint4* Wf0 = Wvf + ((long)n8g*K16)*32 + lane;
        const uint4* Wf1 = Wvf + ((long)(n8g+1)*K16)*32 + lane;

        float acc[2][4];
        #pragma unroll
        for (int j = 0; j < 2; ++j)
            #pragma unroll
            for (int r = 0; r < 4; ++r) acc[j][r] = 0.f;

        #pragma unroll 8
        for (int k16 = 0; k16 < K16; ++k16) {
            uint4 b0 = Wf0[k16*32];
            uint4 b1 = Wf1[k16*32];
            uint32_t ah[4], al[4];
            LDSM4(ah[0],ah[1],ah[2],ah[3], aH + k16*32);
            LDSM4(al[0],al[1],al[2],al[3], aL + k16*32);
            MMA_F16(acc[0], ah, b0.x, b0.y);
            MMA_F16(acc[0], ah, b0.z, b0.w);
            MMA_F16(acc[0], al, b0.x, b0.y);
            MMA_F16(acc[1], ah, b1.x, b1.y);
            MMA_F16(acc[1], ah, b1.z, b1.w);
            MMA_F16(acc[1], al, b1.x, b1.y);
        }

        const int mrow = mw*16 + (lane >> 2);
        #pragma unroll
        for (int j = 0; j < 2; ++j) {
            int n = n0 + nw*16 + j*8 + 2*(lane & 3);
            *(float2*)(F + ((long)b*KTOK + mrow)*NCOLS + n)
                = make_float2(acc[j][0], acc[j][1]);
            *(float2*)(F + ((long)b*KTOK + mrow + 8)*NCOLS + n)
                = make_float2(acc[j][2], acc[j][3]);
        }
    }

    grid_barrier();

    // ---------- stage 3: outF = F @ Wo^T (blocks < 128) ----------
    if (bid < 128) {
        constexpr int KIN = 256, NCOLS = 512, PA = KIN*2 + 16, K16 = KIN/16, F4R = KIN/4;
        const int n0 = (bid & 7) * 64;
        const int b  = bid >> 3;
        const float* Ab = F + (long)b*KTOK*KIN;

        #pragma unroll
        for (int p = 0; p < 32*F4R/256; ++p) {
            int lin = tid + p*256;
            int r  = lin / F4R;
            int c4 = lin % F4R;
            float4 v = *(const float4*)(Ab + r*KIN + 4*c4);
            uint2 hi, lo; cvt_split4h(v, hi, lo);
            *(uint2*)(sm + r*PA + 8*c4)         = hi;
            *(uint2*)(sm + 32*PA + r*PA + 8*c4) = lo;
        }
        __syncthreads();

        const uint32_t aH = smb + (mw*16 + (lane & 15))*PA + (lane >> 4)*16;
        const uint32_t aL = aH + 32*PA;
        const int n8g = (n0 >> 3) + nw*2;
        const uint4* Wf0 = Wof + ((long)n8g*K16)*32 + lane;
        const uint4* Wf1 = Wof + ((long)(n8g+1)*K16)*32 + lane;

        float acc[2][4];
        #pragma unroll
        for (int j = 0; j < 2; ++j)
            #pragma unroll
            for (int r = 0; r < 4; ++r) acc[j][r] = 0.f;

        #pragma unroll 8
        for (int k16 = 0; k16 < K16; ++k16) {
            uint4 b0 = Wf0[k16*32];
            uint4 b1 = Wf1[k16*32];
            uint32_t ah[4], al[4];
            LDSM4(ah[0],ah[1],ah[2],ah[3], aH + k16*32);
            LDSM4(al[0],al[1],al[2],al[3], aL + k16*32);
            MMA_F16(acc[0], ah, b0.x, b0.y);
            MMA_F16(acc[0], ah, b0.z, b0.w);
            MMA_F16(acc[0], al, b0.x, b0.y);
            MMA_F16(acc[1], ah, b1.x, b1.y);
            MMA_F16(acc[1], ah, b1.z, b1.w);
            MMA_F16(acc[1], al, b1.x, b1.y);
        }

        const int mrow = mw*16 + (lane >> 2);
        #pragma unroll
        for (int j = 0; j < 2; ++j) {
            int n = n0 + nw*16 + j*8 + 2*(lane & 3);
            *(float2*)(outF + ((long)b*KTOK + mrow)*NCOLS + n)
                = make_float2(acc[j][0], acc[j][1]);
            *(float2*)(outF + ((long)b*KTOK + mrow + 8)*NCOLS + n)
                = make_float2(acc[j][2], acc[j][3]);
        }
    }

    grid_barrier();

    // ---------- stage 4: L2-normalize (rows 2*bid, 2*bid+1) ----------
    {
        float* red = (float*)sm;
        const int half = tid >> 7;        // 0 or 1
        const int t    = tid & 127;
        const int row  = bid*2 + half;
        float* p = outF + (long)row * DIM;
        float v[4]; float ss = 0.f;
        #pragma unroll
        for (int i = 0; i < 4; i++) { v[i] = p[t + i*128]; ss += v[i]*v[i]; }
        red[tid] = ss;
        __syncthreads();
        #pragma unroll
        for (int s = 64; s > 0; s >>= 1) {
            if (t < s) red[half*128 + t] += red[half*128 + t + s];
            __syncthreads();
        }
        float inv = 1.f / (sqrtf(red[half*128]) + 1e-8f);
        #pragma unroll
        for (int i = 0; i < 4; i++) p[t + i*128] = v[i] * inv;
    }
}

extern "C" void kernel_launch(void* const* d_in, const int* in_sizes, int n_in,
                              void* d_out, int out_size)
{
    const float* E  = (const float*)d_in[0];
    const float* T  = (const float*)d_in[1];
    const float* P  = (const float*)d_in[2];
    const float* Wq = (const float*)d_in[3];
    const float* Wk = (const float*)d_in[4];
    const float* Wv = (const float*)d_in[5];
    const float* Wo = (const float*)d_in[6];

    float* outF = (float*)d_out;
    float* outA = (float*)d_out + (long)BATCH*KTOK*DIM;

    float *pGp, *pG, *pF, *pRows;
    __half* pQkh;
    uint4 *pWvf, *pWof;
    cudaGetSymbolAddress((void**)&pQkh,  g_Qkh);
    cudaGetSymbolAddress((void**)&pGp,   g_Gp);
    cudaGetSymbolAddress((void**)&pG,    g_G);
    cudaGetSymbolAddress((void**)&pF,    g_F);
    cudaGetSymbolAddress((void**)&pRows, g_rows);
    cudaGetSymbolAddress((void**)&pWvf,  g_Wvf);
    cudaGetSymbolAddress((void**)&pWof,  g_Wof);

    const int MT_SMEM = 64*(512*2+16);   // 66560 (stage-2 A staging is largest)

    cudaFuncSetAttribute(fused_attn4,
        cudaFuncAttributeMaxDynamicSharedMemorySize, SMEM_FUSED);
    cudaFuncSetAttribute(mega_tail,
        cudaFuncAttributeMaxDynamicSharedMemorySize, MT_SMEM);

    dim3 blk(256);

    // 1) prep W fragments (blocks 0-255) + Qk projection (blocks 256-319)
    prep_proj<<<320, blk>>>(T, Wq, Wk, Wv, Wo, pQkh, pWvf, pWof);

    // 2) FUSED: expS/A(unnorm) + row-sum partials + G partials
    fused_attn4<<<dim3(SPLITS, BATCH), blk, SMEM_FUSED>>>(
        pQkh, E, P, outA, pGp, pRows);

    // 3) mega tail: G-reduce + A-rescale | F=G@Wv^T | outF=F@Wo^T | normalize
    mega_tail<<<NBLK_MT, blk, MT_SMEM>>>(
        pGp, pG, pRows, outA, pWvf, pWof, pF, outF);
}